// round 4
// baseline (speedup 1.0000x reference)
#include <cuda_runtime.h>

// ---------------------------------------------------------------------------
// VentralModel pooling, round 4: software-pipelined window stream.
//   modulus_kernel : m = sqrt(re^2+im^2), 2x float4/thread -> g_m (L2-res)
//   pool_kernel    : 2100 chunk-tasks x 512 thr, prefetch-next-4 pipeline
//   finalize_kernel: combine chunks, divide by nonzero count, write out
// Output: [s*1200 + o*300 + w] s=0..3, then [4800 + w] mean luminance.
// ---------------------------------------------------------------------------

#define ZT 1e-20f

// modulus scratch: s0 @0 (4*262144), s1 @1048576 (4*65536),
// s2 @1310720 (4*16384), s3 @1376256 (4*4096)
static __device__ float g_m[1392640];
// per-task partials: [task*8 + {a0,a1,a2,a3,aL,cf}]
static __device__ float g_part[2100 * 8];

// Each thread: 2 independent float4 = 4 complex values -> 4 moduli (float4 store).
// Segment boundaries (pairs 1048576/1310720/1376256) are all multiples of 4,
// so a thread's 4 moduli never straddle segments.
__global__ __launch_bounds__(256) void modulus_kernel(
    const float* __restrict__ p0, const float* __restrict__ p1,
    const float* __restrict__ p2, const float* __restrict__ p3)
{
    int t = blockIdx.x * blockDim.x + threadIdx.x;   // 348160 threads
    int pi = t * 4;                                  // first modulus index
    const float4* p;
    int off;                                         // float4 offset into source
    if (pi < 1048576)      { p = (const float4*)p0; off = t * 2; }
    else if (pi < 1310720) { p = (const float4*)p1; off = t * 2 - (1048576 >> 1); }
    else if (pi < 1376256) { p = (const float4*)p2; off = t * 2 - (1310720 >> 1); }
    else                   { p = (const float4*)p3; off = t * 2 - (1376256 >> 1); }
    float4 a = p[off];
    float4 b = p[off + 1];
    float4 r;
    r.x = sqrtf(a.x * a.x + a.y * a.y);
    r.y = sqrtf(a.z * a.z + a.w * a.w);
    r.z = sqrtf(b.x * b.x + b.y * b.y);
    r.w = sqrtf(b.z * b.z + b.w * b.w);
    *(float4*)(g_m + pi) = r;
}

static __device__ __forceinline__ float warp_red(float v) {
    #pragma unroll
    for (int o = 16; o > 0; o >>= 1)
        v += __shfl_down_sync(0xffffffffu, v, o);
    return v;
}

#define GROUP(Q, IDX)                                                          \
    do {                                                                       \
        float4 q_ = (Q); int i_ = (IDX);                                       \
        cf += (q_.x > ZT ? 1.f : 0.f) + (q_.y > ZT ? 1.f : 0.f)                \
            + (q_.z > ZT ? 1.f : 0.f) + (q_.w > ZT ? 1.f : 0.f);               \
        if (q_.x != 0.f || q_.y != 0.f || q_.z != 0.f || q_.w != 0.f) {        \
            float4 v_;                                                         \
            v_ = m0[i_]; a0 += q_.x*v_.x + q_.y*v_.y + q_.z*v_.z + q_.w*v_.w;  \
            v_ = m1[i_]; a1 += q_.x*v_.x + q_.y*v_.y + q_.z*v_.z + q_.w*v_.w;  \
            v_ = m2[i_]; a2 += q_.x*v_.x + q_.y*v_.y + q_.z*v_.z + q_.w*v_.w;  \
            v_ = m3[i_]; a3 += q_.x*v_.x + q_.y*v_.y + q_.z*v_.z + q_.w*v_.w;  \
            if (do_img) {                                                      \
                v_ = iv[i_]; aL += q_.x*v_.x + q_.y*v_.y + q_.z*v_.z + q_.w*v_.w; \
            }                                                                  \
        }                                                                      \
    } while (0)

// Task map (2100 blocks of 512 threads):
//  [0,1200)    scale0: w=t>>2, q=t&3, nv=16384 float4 (256 KB)
//  [1200,1500) scale1: nv=16384 (256 KB)
//  [1500,1800) scale2: nv=4096  (64 KB)
//  [1800,2100) scale3: nv=1024  (16 KB)
__global__ __launch_bounds__(512) void pool_kernel(
    const float* __restrict__ w0, const float* __restrict__ w1,
    const float* __restrict__ w2, const float* __restrict__ w3,
    const float* __restrict__ img)
{
    int t = blockIdx.x;
    const float* winp; const float* mp;
    int n, nv_c, cw_off, m_off;
    bool do_img = false;

    if (t < 1200) {
        int w = t >> 2, q = t & 3;
        winp = w0; mp = g_m; n = 262144;
        nv_c = 16384; cw_off = w * 65536 + q * 16384; m_off = q * 16384;
        do_img = true;
    } else if (t < 1500) {
        int w = t - 1200;
        winp = w1; mp = g_m + 1048576; n = 65536;
        nv_c = 16384; cw_off = w * 16384; m_off = 0;
    } else if (t < 1800) {
        int w = t - 1500;
        winp = w2; mp = g_m + 1310720; n = 16384;
        nv_c = 4096; cw_off = w * 4096; m_off = 0;
    } else {
        int w = t - 1800;
        winp = w3; mp = g_m + 1376256; n = 4096;
        nv_c = 1024; cw_off = w * 1024; m_off = 0;
    }

    const float4* wv = (const float4*)winp + cw_off;
    const float4* m0 = (const float4*)mp + m_off;
    const float4* m1 = (const float4*)(mp + n) + m_off;
    const float4* m2 = (const float4*)(mp + 2 * n) + m_off;
    const float4* m3 = (const float4*)(mp + 3 * n) + m_off;
    const float4* iv = (const float4*)img + m_off;

    float a0 = 0.f, a1 = 0.f, a2 = 0.f, a3 = 0.f, aL = 0.f, cf = 0.f;

    if (nv_c >= 2048) {
        // software pipeline: window loads for iteration k+1 are issued before
        // the branchy consume of iteration k, hiding the streaming latency.
        int i = threadIdx.x;
        float4 q0 = __ldcs(wv + i);
        float4 q1 = __ldcs(wv + i + 512);
        float4 q2 = __ldcs(wv + i + 1024);
        float4 q3 = __ldcs(wv + i + 1536);
        while (i + 2048 < nv_c) {
            int j = i + 2048;
            float4 r0 = __ldcs(wv + j);
            float4 r1 = __ldcs(wv + j + 512);
            float4 r2 = __ldcs(wv + j + 1024);
            float4 r3 = __ldcs(wv + j + 1536);
            GROUP(q0, i);
            GROUP(q1, i + 512);
            GROUP(q2, i + 1024);
            GROUP(q3, i + 1536);
            q0 = r0; q1 = r1; q2 = r2; q3 = r3;
            i = j;
        }
        GROUP(q0, i);
        GROUP(q1, i + 512);
        GROUP(q2, i + 1024);
        GROUP(q3, i + 1536);
    } else {
        for (int i = threadIdx.x; i < nv_c; i += 512) {
            float4 q0 = __ldcs(wv + i);
            GROUP(q0, i);
        }
    }

    // block reduction (16 warps)
    __shared__ float sm[16][6];
    int lane = threadIdx.x & 31, wid = threadIdx.x >> 5;
    a0 = warp_red(a0); a1 = warp_red(a1); a2 = warp_red(a2);
    a3 = warp_red(a3); aL = warp_red(aL); cf = warp_red(cf);
    if (lane == 0) {
        sm[wid][0] = a0; sm[wid][1] = a1; sm[wid][2] = a2;
        sm[wid][3] = a3; sm[wid][4] = aL; sm[wid][5] = cf;
    }
    __syncthreads();
    if (threadIdx.x < 6) {
        float r = 0.f;
        #pragma unroll
        for (int k = 0; k < 16; k++) r += sm[k][threadIdx.x];
        g_part[t * 8 + threadIdx.x] = r;
    }
}

__global__ __launch_bounds__(256) void finalize_kernel(float* __restrict__ out)
{
    int tid = blockIdx.x * blockDim.x + threadIdx.x;
    if (tid >= 1200) return;
    int sc = tid / 300, w = tid % 300;
    float s0 = 0.f, s1 = 0.f, s2 = 0.f, s3 = 0.f, sL = 0.f, cnt = 0.f;
    if (sc == 0) {
        #pragma unroll
        for (int q = 0; q < 4; q++) {
            const float* p = g_part + (w * 4 + q) * 8;
            s0 += p[0]; s1 += p[1]; s2 += p[2];
            s3 += p[3]; sL += p[4]; cnt += p[5];
        }
    } else {
        const float* p = g_part + (900 + sc * 300 + w) * 8;
        s0 = p[0]; s1 = p[1]; s2 = p[2]; s3 = p[3]; sL = p[4]; cnt = p[5];
    }
    float inv = 1.f / cnt;
    int ob = sc * 1200;
    out[ob + 0 * 300 + w] = s0 * inv;
    out[ob + 1 * 300 + w] = s1 * inv;
    out[ob + 2 * 300 + w] = s2 * inv;
    out[ob + 3 * 300 + w] = s3 * inv;
    if (sc == 0) out[4800 + w] = sL * inv;
}

extern "C" void kernel_launch(void* const* d_in, const int* in_sizes, int n_in,
                              void* d_out, int out_size)
{
    const float *img = nullptr, *p0 = nullptr, *p1 = nullptr, *p2 = nullptr, *p3 = nullptr;
    const float *w0 = nullptr, *w1 = nullptr, *w2 = nullptr, *w3 = nullptr;

    for (int i = 0; i < n_in; i++) {
        switch (in_sizes[i]) {
            case 262144:   img = (const float*)d_in[i]; break;   // image 512^2
            case 2097152:  p0  = (const float*)d_in[i]; break;   // pyr0
            case 78643200: w0  = (const float*)d_in[i]; break;   // win0
            case 524288:   p1  = (const float*)d_in[i]; break;   // pyr1
            case 19660800: w1  = (const float*)d_in[i]; break;   // win1
            case 131072:   p2  = (const float*)d_in[i]; break;   // pyr2
            case 4915200:  w2  = (const float*)d_in[i]; break;   // win2
            case 32768:    p3  = (const float*)d_in[i]; break;   // pyr3
            case 1228800:  w3  = (const float*)d_in[i]; break;   // win3
        }
    }

    modulus_kernel<<<1360, 256>>>(p0, p1, p2, p3);   // 348160 threads, 4 moduli each
    pool_kernel<<<2100, 512>>>(w0, w1, w2, w3, img);
    finalize_kernel<<<5, 256>>>((float*)d_out);
}

// round 5
// speedup vs baseline: 1.3058x; 1.3058x over previous
#include <cuda_runtime.h>

// ---------------------------------------------------------------------------
// VentralModel pooling, round 5: R3 structure, 256-thr blocks, 128KB chunks.
//   modulus_kernel : m = sqrt(re^2+im^2) -> g_m (5.6 MB, L2-resident)
//   pool_kernel    : 3600 chunk-tasks x 256 thr; partials -> g_part
//   finalize_kernel: combine chunks, divide by nonzero count, write out
// Output: [s*1200 + o*300 + w] s=0..3, then [4800 + w] mean luminance.
// ---------------------------------------------------------------------------

#define ZT 1e-20f

// modulus scratch: s0 @0 (4*262144), s1 @1048576 (4*65536),
// s2 @1310720 (4*16384), s3 @1376256 (4*4096)
static __device__ float g_m[1392640];
// per-task partials: [task*8 + {a0,a1,a2,a3,aL,cf}]
static __device__ float g_part[3600 * 8];

// Each thread: one float4 = 2 complex values -> 2 moduli (float2 store). (R3 version)
__global__ __launch_bounds__(256) void modulus_kernel(
    const float* __restrict__ p0, const float* __restrict__ p1,
    const float* __restrict__ p2, const float* __restrict__ p3)
{
    int i = blockIdx.x * blockDim.x + threadIdx.x;   // 696320 threads total
    int pi = i * 2;                                  // pair (modulus) index
    const float4* p;
    int off;
    if (pi < 1048576)      { p = (const float4*)p0; off = i; }
    else if (pi < 1310720) { p = (const float4*)p1; off = i - (1048576 >> 1); }
    else if (pi < 1376256) { p = (const float4*)p2; off = i - (1310720 >> 1); }
    else                   { p = (const float4*)p3; off = i - (1376256 >> 1); }
    float4 v = p[off];
    float2 r;
    r.x = sqrtf(v.x * v.x + v.y * v.y);
    r.y = sqrtf(v.z * v.z + v.w * v.w);
    *(float2*)(g_m + pi) = r;
}

static __device__ __forceinline__ float warp_red(float v) {
    #pragma unroll
    for (int o = 16; o > 0; o >>= 1)
        v += __shfl_down_sync(0xffffffffu, v, o);
    return v;
}

#define GROUP(Q, IDX)                                                          \
    do {                                                                       \
        float4 q_ = (Q); int i_ = (IDX);                                       \
        cf += (q_.x > ZT ? 1.f : 0.f) + (q_.y > ZT ? 1.f : 0.f)                \
            + (q_.z > ZT ? 1.f : 0.f) + (q_.w > ZT ? 1.f : 0.f);               \
        if (q_.x != 0.f || q_.y != 0.f || q_.z != 0.f || q_.w != 0.f) {        \
            float4 v_;                                                         \
            v_ = m0[i_]; a0 += q_.x*v_.x + q_.y*v_.y + q_.z*v_.z + q_.w*v_.w;  \
            v_ = m1[i_]; a1 += q_.x*v_.x + q_.y*v_.y + q_.z*v_.z + q_.w*v_.w;  \
            v_ = m2[i_]; a2 += q_.x*v_.x + q_.y*v_.y + q_.z*v_.z + q_.w*v_.w;  \
            v_ = m3[i_]; a3 += q_.x*v_.x + q_.y*v_.y + q_.z*v_.z + q_.w*v_.w;  \
            if (do_img) {                                                      \
                v_ = iv[i_]; aL += q_.x*v_.x + q_.y*v_.y + q_.z*v_.z + q_.w*v_.w; \
            }                                                                  \
        }                                                                      \
    } while (0)

// Task map (3600 blocks of 256 threads), chunk = 8192 float4 (128 KB):
//  [0,2400)    scale0: w=t>>3, q=t&7, nv=8192
//  [2400,3000) scale1: w=(t-2400)>>1, q=(t-2400)&1, nv=8192
//  [3000,3300) scale2: nv=4096  (64 KB)
//  [3300,3600) scale3: nv=1024  (16 KB)
__global__ __launch_bounds__(256) void pool_kernel(
    const float* __restrict__ w0, const float* __restrict__ w1,
    const float* __restrict__ w2, const float* __restrict__ w3,
    const float* __restrict__ img)
{
    int t = blockIdx.x;
    const float* winp; const float* mp;
    int n, nv_c, cw_off, m_off;
    bool do_img = false;

    if (t < 2400) {
        int w = t >> 3, q = t & 7;
        winp = w0; mp = g_m; n = 262144;
        nv_c = 8192; cw_off = w * 65536 + q * 8192; m_off = q * 8192;
        do_img = true;
    } else if (t < 3000) {
        int u = t - 2400, w = u >> 1, q = u & 1;
        winp = w1; mp = g_m + 1048576; n = 65536;
        nv_c = 8192; cw_off = w * 16384 + q * 8192; m_off = q * 8192;
    } else if (t < 3300) {
        int w = t - 3000;
        winp = w2; mp = g_m + 1310720; n = 16384;
        nv_c = 4096; cw_off = w * 4096; m_off = 0;
    } else {
        int w = t - 3300;
        winp = w3; mp = g_m + 1376256; n = 4096;
        nv_c = 1024; cw_off = w * 1024; m_off = 0;
    }

    const float4* wv = (const float4*)winp + cw_off;
    const float4* m0 = (const float4*)mp + m_off;
    const float4* m1 = (const float4*)(mp + n) + m_off;
    const float4* m2 = (const float4*)(mp + 2 * n) + m_off;
    const float4* m3 = (const float4*)(mp + 3 * n) + m_off;
    const float4* iv = (const float4*)img + m_off;

    float a0 = 0.f, a1 = 0.f, a2 = 0.f, a3 = 0.f, aL = 0.f, cf = 0.f;

    // unroll x4 (nv_c % 1024 == 0 for all tasks): 4 window loads in flight
    for (int i = threadIdx.x; i < nv_c; i += 1024) {
        float4 q0 = __ldcs(wv + i);
        float4 q1 = __ldcs(wv + i + 256);
        float4 q2 = __ldcs(wv + i + 512);
        float4 q3 = __ldcs(wv + i + 768);
        GROUP(q0, i);
        GROUP(q1, i + 256);
        GROUP(q2, i + 512);
        GROUP(q3, i + 768);
    }

    // block reduction (8 warps)
    __shared__ float sm[8][6];
    int lane = threadIdx.x & 31, wid = threadIdx.x >> 5;
    a0 = warp_red(a0); a1 = warp_red(a1); a2 = warp_red(a2);
    a3 = warp_red(a3); aL = warp_red(aL); cf = warp_red(cf);
    if (lane == 0) {
        sm[wid][0] = a0; sm[wid][1] = a1; sm[wid][2] = a2;
        sm[wid][3] = a3; sm[wid][4] = aL; sm[wid][5] = cf;
    }
    __syncthreads();
    if (threadIdx.x < 6) {
        float r = 0.f;
        #pragma unroll
        for (int k = 0; k < 8; k++) r += sm[k][threadIdx.x];
        g_part[t * 8 + threadIdx.x] = r;
    }
}

__global__ __launch_bounds__(256) void finalize_kernel(float* __restrict__ out)
{
    int tid = blockIdx.x * blockDim.x + threadIdx.x;
    if (tid >= 1200) return;
    int sc = tid / 300, w = tid % 300;
    float s0 = 0.f, s1 = 0.f, s2 = 0.f, s3 = 0.f, sL = 0.f, cnt = 0.f;
    if (sc == 0) {
        #pragma unroll
        for (int q = 0; q < 8; q++) {
            const float* p = g_part + (w * 8 + q) * 8;
            s0 += p[0]; s1 += p[1]; s2 += p[2];
            s3 += p[3]; sL += p[4]; cnt += p[5];
        }
    } else if (sc == 1) {
        #pragma unroll
        for (int q = 0; q < 2; q++) {
            const float* p = g_part + (2400 + w * 2 + q) * 8;
            s0 += p[0]; s1 += p[1]; s2 += p[2];
            s3 += p[3]; sL += p[4]; cnt += p[5];
        }
    } else {
        const float* p = g_part + (2400 + sc * 300 + w) * 8;  // sc2->3000+w, sc3->3300+w
        s0 = p[0]; s1 = p[1]; s2 = p[2]; s3 = p[3]; sL = p[4]; cnt = p[5];
    }
    float inv = 1.f / cnt;
    int ob = sc * 1200;
    out[ob + 0 * 300 + w] = s0 * inv;
    out[ob + 1 * 300 + w] = s1 * inv;
    out[ob + 2 * 300 + w] = s2 * inv;
    out[ob + 3 * 300 + w] = s3 * inv;
    if (sc == 0) out[4800 + w] = sL * inv;
}

extern "C" void kernel_launch(void* const* d_in, const int* in_sizes, int n_in,
                              void* d_out, int out_size)
{
    const float *img = nullptr, *p0 = nullptr, *p1 = nullptr, *p2 = nullptr, *p3 = nullptr;
    const float *w0 = nullptr, *w1 = nullptr, *w2 = nullptr, *w3 = nullptr;

    for (int i = 0; i < n_in; i++) {
        switch (in_sizes[i]) {
            case 262144:   img = (const float*)d_in[i]; break;   // image 512^2
            case 2097152:  p0  = (const float*)d_in[i]; break;   // pyr0
            case 78643200: w0  = (const float*)d_in[i]; break;   // win0
            case 524288:   p1  = (const float*)d_in[i]; break;   // pyr1
            case 19660800: w1  = (const float*)d_in[i]; break;   // win1
            case 131072:   p2  = (const float*)d_in[i]; break;   // pyr2
            case 4915200:  w2  = (const float*)d_in[i]; break;   // win2
            case 32768:    p3  = (const float*)d_in[i]; break;   // pyr3
            case 1228800:  w3  = (const float*)d_in[i]; break;   // win3
        }
    }

    modulus_kernel<<<2720, 256>>>(p0, p1, p2, p3);   // 696320 threads
    pool_kernel<<<3600, 256>>>(w0, w1, w2, w3, img);
    finalize_kernel<<<5, 256>>>((float*)d_out);
}

// round 6
// speedup vs baseline: 1.3395x; 1.0258x over previous
#include <cuda_runtime.h>

// ---------------------------------------------------------------------------
// VentralModel pooling, round 6: R3 skeleton + cheap zero-group fast path.
// Window values are >= 0 and thresholded (0 or >= 1e-6), so:
//   group all-zero  <=>  sum == 0   (3 FADD + 1 FSETP)
//   count(w > 1e-20) == count(w > 0), computed only in nonzero groups.
// Output: [s*1200 + o*300 + w] s=0..3, then [4800 + w] mean luminance.
// ---------------------------------------------------------------------------

// modulus scratch: s0 @0 (4*262144), s1 @1048576 (4*65536),
// s2 @1310720 (4*16384), s3 @1376256 (4*4096)
static __device__ float g_m[1392640];
// per-task partials: [task*8 + {a0,a1,a2,a3,aL,cf}]
static __device__ float g_part[2100 * 8];

// Each thread: one float4 = 2 complex values -> 2 moduli (float2 store).
__global__ __launch_bounds__(256) void modulus_kernel(
    const float* __restrict__ p0, const float* __restrict__ p1,
    const float* __restrict__ p2, const float* __restrict__ p3)
{
    int i = blockIdx.x * blockDim.x + threadIdx.x;   // 696320 threads total
    int pi = i * 2;                                  // pair (modulus) index
    const float4* p;
    int off;
    if (pi < 1048576)      { p = (const float4*)p0; off = i; }
    else if (pi < 1310720) { p = (const float4*)p1; off = i - (1048576 >> 1); }
    else if (pi < 1376256) { p = (const float4*)p2; off = i - (1310720 >> 1); }
    else                   { p = (const float4*)p3; off = i - (1376256 >> 1); }
    float4 v = p[off];
    float2 r;
    r.x = sqrtf(v.x * v.x + v.y * v.y);
    r.y = sqrtf(v.z * v.z + v.w * v.w);
    *(float2*)(g_m + pi) = r;
}

static __device__ __forceinline__ float warp_red(float v) {
    #pragma unroll
    for (int o = 16; o > 0; o >>= 1)
        v += __shfl_down_sync(0xffffffffu, v, o);
    return v;
}

// Window values are non-negative; sum==0 <=> all four are zero.
// cf counts strictly-positive elements, only evaluated in nonzero groups.
#define GROUP(Q, IDX)                                                          \
    do {                                                                       \
        float4 q_ = (Q); int i_ = (IDX);                                       \
        float s_ = (q_.x + q_.y) + (q_.z + q_.w);                              \
        if (s_ > 0.f) {                                                        \
            cf += (q_.x > 0.f ? 1.f : 0.f) + (q_.y > 0.f ? 1.f : 0.f)          \
                + (q_.z > 0.f ? 1.f : 0.f) + (q_.w > 0.f ? 1.f : 0.f);         \
            float4 v_;                                                         \
            v_ = m0[i_]; a0 += q_.x*v_.x + q_.y*v_.y + q_.z*v_.z + q_.w*v_.w;  \
            v_ = m1[i_]; a1 += q_.x*v_.x + q_.y*v_.y + q_.z*v_.z + q_.w*v_.w;  \
            v_ = m2[i_]; a2 += q_.x*v_.x + q_.y*v_.y + q_.z*v_.z + q_.w*v_.w;  \
            v_ = m3[i_]; a3 += q_.x*v_.x + q_.y*v_.y + q_.z*v_.z + q_.w*v_.w;  \
            if (do_img) {                                                      \
                v_ = iv[i_]; aL += q_.x*v_.x + q_.y*v_.y + q_.z*v_.z + q_.w*v_.w; \
            }                                                                  \
        }                                                                      \
    } while (0)

// Task map (2100 blocks of 512 threads):
//  [0,1200)    scale0: w=t>>2, q=t&3, nv=16384 float4 (256 KB)
//  [1200,1500) scale1: nv=16384 (256 KB)
//  [1500,1800) scale2: nv=4096  (64 KB)
//  [1800,2100) scale3: nv=1024  (16 KB)
__global__ __launch_bounds__(512) void pool_kernel(
    const float* __restrict__ w0, const float* __restrict__ w1,
    const float* __restrict__ w2, const float* __restrict__ w3,
    const float* __restrict__ img)
{
    int t = blockIdx.x;
    const float* winp; const float* mp;
    int n, nv_c, cw_off, m_off;
    bool do_img = false;

    if (t < 1200) {
        int w = t >> 2, q = t & 3;
        winp = w0; mp = g_m; n = 262144;
        nv_c = 16384; cw_off = w * 65536 + q * 16384; m_off = q * 16384;
        do_img = true;
    } else if (t < 1500) {
        int w = t - 1200;
        winp = w1; mp = g_m + 1048576; n = 65536;
        nv_c = 16384; cw_off = w * 16384; m_off = 0;
    } else if (t < 1800) {
        int w = t - 1500;
        winp = w2; mp = g_m + 1310720; n = 16384;
        nv_c = 4096; cw_off = w * 4096; m_off = 0;
    } else {
        int w = t - 1800;
        winp = w3; mp = g_m + 1376256; n = 4096;
        nv_c = 1024; cw_off = w * 1024; m_off = 0;
    }

    const float4* wv = (const float4*)winp + cw_off;
    const float4* m0 = (const float4*)mp + m_off;
    const float4* m1 = (const float4*)(mp + n) + m_off;
    const float4* m2 = (const float4*)(mp + 2 * n) + m_off;
    const float4* m3 = (const float4*)(mp + 3 * n) + m_off;
    const float4* iv = (const float4*)img + m_off;

    float a0 = 0.f, a1 = 0.f, a2 = 0.f, a3 = 0.f, aL = 0.f, cf = 0.f;

    if (nv_c >= 2048) {
        // unroll x4, no guards (nv_c % 2048 == 0): 4 window loads in flight
        for (int i = threadIdx.x; i < nv_c; i += 2048) {
            float4 q0 = __ldcs(wv + i);
            float4 q1 = __ldcs(wv + i + 512);
            float4 q2 = __ldcs(wv + i + 1024);
            float4 q3 = __ldcs(wv + i + 1536);
            GROUP(q0, i);
            GROUP(q1, i + 512);
            GROUP(q2, i + 1024);
            GROUP(q3, i + 1536);
        }
    } else {
        for (int i = threadIdx.x; i < nv_c; i += 512) {
            float4 q0 = __ldcs(wv + i);
            GROUP(q0, i);
        }
    }

    // block reduction (16 warps)
    __shared__ float sm[16][6];
    int lane = threadIdx.x & 31, wid = threadIdx.x >> 5;
    a0 = warp_red(a0); a1 = warp_red(a1); a2 = warp_red(a2);
    a3 = warp_red(a3); aL = warp_red(aL); cf = warp_red(cf);
    if (lane == 0) {
        sm[wid][0] = a0; sm[wid][1] = a1; sm[wid][2] = a2;
        sm[wid][3] = a3; sm[wid][4] = aL; sm[wid][5] = cf;
    }
    __syncthreads();
    if (threadIdx.x < 6) {
        float r = 0.f;
        #pragma unroll
        for (int k = 0; k < 16; k++) r += sm[k][threadIdx.x];
        g_part[t * 8 + threadIdx.x] = r;
    }
}

__global__ __launch_bounds__(256) void finalize_kernel(float* __restrict__ out)
{
    int tid = blockIdx.x * blockDim.x + threadIdx.x;
    if (tid >= 1200) return;
    int sc = tid / 300, w = tid % 300;
    float s0 = 0.f, s1 = 0.f, s2 = 0.f, s3 = 0.f, sL = 0.f, cnt = 0.f;
    if (sc == 0) {
        #pragma unroll
        for (int q = 0; q < 4; q++) {
            const float* p = g_part + (w * 4 + q) * 8;
            s0 += p[0]; s1 += p[1]; s2 += p[2];
            s3 += p[3]; sL += p[4]; cnt += p[5];
        }
    } else {
        const float* p = g_part + (900 + sc * 300 + w) * 8;  // sc1->1200+w, sc2->1500+w, sc3->1800+w
        s0 = p[0]; s1 = p[1]; s2 = p[2]; s3 = p[3]; sL = p[4]; cnt = p[5];
    }
    float inv = 1.f / cnt;
    int ob = sc * 1200;
    out[ob + 0 * 300 + w] = s0 * inv;
    out[ob + 1 * 300 + w] = s1 * inv;
    out[ob + 2 * 300 + w] = s2 * inv;
    out[ob + 3 * 300 + w] = s3 * inv;
    if (sc == 0) out[4800 + w] = sL * inv;
}

extern "C" void kernel_launch(void* const* d_in, const int* in_sizes, int n_in,
                              void* d_out, int out_size)
{
    const float *img = nullptr, *p0 = nullptr, *p1 = nullptr, *p2 = nullptr, *p3 = nullptr;
    const float *w0 = nullptr, *w1 = nullptr, *w2 = nullptr, *w3 = nullptr;

    for (int i = 0; i < n_in; i++) {
        switch (in_sizes[i]) {
            case 262144:   img = (const float*)d_in[i]; break;   // image 512^2
            case 2097152:  p0  = (const float*)d_in[i]; break;   // pyr0
            case 78643200: w0  = (const float*)d_in[i]; break;   // win0
            case 524288:   p1  = (const float*)d_in[i]; break;   // pyr1
            case 19660800: w1  = (const float*)d_in[i]; break;   // win1
            case 131072:   p2  = (const float*)d_in[i]; break;   // pyr2
            case 4915200:  w2  = (const float*)d_in[i]; break;   // win2
            case 32768:    p3  = (const float*)d_in[i]; break;   // pyr3
            case 1228800:  w3  = (const float*)d_in[i]; break;   // win3
        }
    }

    modulus_kernel<<<2720, 256>>>(p0, p1, p2, p3);   // 696320 threads
    pool_kernel<<<2100, 512>>>(w0, w1, w2, w3, img);
    finalize_kernel<<<5, 256>>>((float*)d_out);
}

// round 7
// speedup vs baseline: 1.3660x; 1.0198x over previous
#include <cuda_runtime.h>
#include <cuda_fp16.h>

// ---------------------------------------------------------------------------
// VentralModel pooling, round 7: fp16 moduli to halve the secondary L2 stream.
//   modulus_kernel : m = sqrt(re^2+im^2) -> g_m as __half (2.8 MB, L2-res)
//   pool_kernel    : 2100 chunk-tasks x 512 thr; windows fp32 streamed,
//                    m loaded as 4x half (LDG.64) per orientation group.
//   finalize_kernel: combine chunks, divide by nonzero count, write out
// Output: [s*1200 + o*300 + w] s=0..3, then [4800 + w] mean luminance.
// ---------------------------------------------------------------------------

// modulus scratch (half): s0 @0 (4*262144), s1 @1048576 (4*65536),
// s2 @1310720 (4*16384), s3 @1376256 (4*4096)
static __device__ __half g_m[1392640];
// per-task partials: [task*8 + {a0,a1,a2,a3,aL,cf}]
static __device__ float g_part[2100 * 8];

// Each thread: one float4 = 2 complex values -> 2 moduli -> one __half2 store.
__global__ __launch_bounds__(256) void modulus_kernel(
    const float* __restrict__ p0, const float* __restrict__ p1,
    const float* __restrict__ p2, const float* __restrict__ p3)
{
    int i = blockIdx.x * blockDim.x + threadIdx.x;   // 696320 threads total
    int pi = i * 2;                                  // pair (modulus) index
    const float4* p;
    int off;
    if (pi < 1048576)      { p = (const float4*)p0; off = i; }
    else if (pi < 1310720) { p = (const float4*)p1; off = i - (1048576 >> 1); }
    else if (pi < 1376256) { p = (const float4*)p2; off = i - (1310720 >> 1); }
    else                   { p = (const float4*)p3; off = i - (1376256 >> 1); }
    float4 v = p[off];
    float rx = sqrtf(v.x * v.x + v.y * v.y);
    float ry = sqrtf(v.z * v.z + v.w * v.w);
    ((__half2*)g_m)[i] = __floats2half2_rn(rx, ry);
}

static __device__ __forceinline__ float warp_red(float v) {
    #pragma unroll
    for (int o = 16; o > 0; o >>= 1)
        v += __shfl_down_sync(0xffffffffu, v, o);
    return v;
}

// Dot of fp32 window group (4 px) with 4 fp16 moduli loaded as one LDG.64.
static __device__ __forceinline__ float dot_h4(const uint2* base, int idx,
                                               float4 q)
{
    uint2 u = __ldg(base + idx);
    __half2 h0 = *(__half2*)&u.x;
    __half2 h1 = *(__half2*)&u.y;
    float2 f0 = __half22float2(h0);
    float2 f1 = __half22float2(h1);
    return q.x * f0.x + q.y * f0.y + q.z * f1.x + q.w * f1.y;
}

// Window values are non-negative; sum==0 <=> all four are zero.
#define GROUP(Q, IDX)                                                          \
    do {                                                                       \
        float4 q_ = (Q); int i_ = (IDX);                                       \
        float s_ = (q_.x + q_.y) + (q_.z + q_.w);                              \
        if (s_ > 0.f) {                                                        \
            cf += (q_.x > 0.f ? 1.f : 0.f) + (q_.y > 0.f ? 1.f : 0.f)          \
                + (q_.z > 0.f ? 1.f : 0.f) + (q_.w > 0.f ? 1.f : 0.f);         \
            a0 += dot_h4(m0, i_, q_);                                          \
            a1 += dot_h4(m1, i_, q_);                                          \
            a2 += dot_h4(m2, i_, q_);                                          \
            a3 += dot_h4(m3, i_, q_);                                          \
            if (do_img) {                                                      \
                float4 v_ = iv[i_];                                            \
                aL += q_.x*v_.x + q_.y*v_.y + q_.z*v_.z + q_.w*v_.w;           \
            }                                                                  \
        }                                                                      \
    } while (0)

// Task map (2100 blocks of 512 threads):
//  [0,1200)    scale0: w=t>>2, q=t&3, nv=16384 float4 (256 KB)
//  [1200,1500) scale1: nv=16384 (256 KB)
//  [1500,1800) scale2: nv=4096  (64 KB)
//  [1800,2100) scale3: nv=1024  (16 KB)
__global__ __launch_bounds__(512) void pool_kernel(
    const float* __restrict__ w0, const float* __restrict__ w1,
    const float* __restrict__ w2, const float* __restrict__ w3,
    const float* __restrict__ img)
{
    int t = blockIdx.x;
    const float* winp; const __half* mh;
    int n, nv_c, cw_off, m_off;
    bool do_img = false;

    if (t < 1200) {
        int w = t >> 2, q = t & 3;
        winp = w0; mh = g_m; n = 262144;
        nv_c = 16384; cw_off = w * 65536 + q * 16384; m_off = q * 16384;
        do_img = true;
    } else if (t < 1500) {
        int w = t - 1200;
        winp = w1; mh = g_m + 1048576; n = 65536;
        nv_c = 16384; cw_off = w * 16384; m_off = 0;
    } else if (t < 1800) {
        int w = t - 1500;
        winp = w2; mh = g_m + 1310720; n = 16384;
        nv_c = 4096; cw_off = w * 4096; m_off = 0;
    } else {
        int w = t - 1800;
        winp = w3; mh = g_m + 1376256; n = 4096;
        nv_c = 1024; cw_off = w * 1024; m_off = 0;
    }

    const float4* wv = (const float4*)winp + cw_off;
    // one uint2 = 4 halves = one 4-pixel group; orientation stride = n/4 uint2
    const uint2* m0 = (const uint2*)mh + m_off;
    const uint2* m1 = (const uint2*)(mh + n) + m_off;
    const uint2* m2 = (const uint2*)(mh + 2 * n) + m_off;
    const uint2* m3 = (const uint2*)(mh + 3 * n) + m_off;
    const float4* iv = (const float4*)img + m_off;

    float a0 = 0.f, a1 = 0.f, a2 = 0.f, a3 = 0.f, aL = 0.f, cf = 0.f;

    if (nv_c >= 2048) {
        // unroll x4, no guards (nv_c % 2048 == 0): 4 window loads in flight
        for (int i = threadIdx.x; i < nv_c; i += 2048) {
            float4 q0 = __ldcs(wv + i);
            float4 q1 = __ldcs(wv + i + 512);
            float4 q2 = __ldcs(wv + i + 1024);
            float4 q3 = __ldcs(wv + i + 1536);
            GROUP(q0, i);
            GROUP(q1, i + 512);
            GROUP(q2, i + 1024);
            GROUP(q3, i + 1536);
        }
    } else {
        for (int i = threadIdx.x; i < nv_c; i += 512) {
            float4 q0 = __ldcs(wv + i);
            GROUP(q0, i);
        }
    }

    // block reduction (16 warps)
    __shared__ float sm[16][6];
    int lane = threadIdx.x & 31, wid = threadIdx.x >> 5;
    a0 = warp_red(a0); a1 = warp_red(a1); a2 = warp_red(a2);
    a3 = warp_red(a3); aL = warp_red(aL); cf = warp_red(cf);
    if (lane == 0) {
        sm[wid][0] = a0; sm[wid][1] = a1; sm[wid][2] = a2;
        sm[wid][3] = a3; sm[wid][4] = aL; sm[wid][5] = cf;
    }
    __syncthreads();
    if (threadIdx.x < 6) {
        float r = 0.f;
        #pragma unroll
        for (int k = 0; k < 16; k++) r += sm[k][threadIdx.x];
        g_part[t * 8 + threadIdx.x] = r;
    }
}

__global__ __launch_bounds__(256) void finalize_kernel(float* __restrict__ out)
{
    int tid = blockIdx.x * blockDim.x + threadIdx.x;
    if (tid >= 1200) return;
    int sc = tid / 300, w = tid % 300;
    float s0 = 0.f, s1 = 0.f, s2 = 0.f, s3 = 0.f, sL = 0.f, cnt = 0.f;
    if (sc == 0) {
        #pragma unroll
        for (int q = 0; q < 4; q++) {
            const float* p = g_part + (w * 4 + q) * 8;
            s0 += p[0]; s1 += p[1]; s2 += p[2];
            s3 += p[3]; sL += p[4]; cnt += p[5];
        }
    } else {
        const float* p = g_part + (900 + sc * 300 + w) * 8;  // sc1->1200+w, sc2->1500+w, sc3->1800+w
        s0 = p[0]; s1 = p[1]; s2 = p[2]; s3 = p[3]; sL = p[4]; cnt = p[5];
    }
    float inv = 1.f / cnt;
    int ob = sc * 1200;
    out[ob + 0 * 300 + w] = s0 * inv;
    out[ob + 1 * 300 + w] = s1 * inv;
    out[ob + 2 * 300 + w] = s2 * inv;
    out[ob + 3 * 300 + w] = s3 * inv;
    if (sc == 0) out[4800 + w] = sL * inv;
}

extern "C" void kernel_launch(void* const* d_in, const int* in_sizes, int n_in,
                              void* d_out, int out_size)
{
    const float *img = nullptr, *p0 = nullptr, *p1 = nullptr, *p2 = nullptr, *p3 = nullptr;
    const float *w0 = nullptr, *w1 = nullptr, *w2 = nullptr, *w3 = nullptr;

    for (int i = 0; i < n_in; i++) {
        switch (in_sizes[i]) {
            case 262144:   img = (const float*)d_in[i]; break;   // image 512^2
            case 2097152:  p0  = (const float*)d_in[i]; break;   // pyr0
            case 78643200: w0  = (const float*)d_in[i]; break;   // win0
            case 524288:   p1  = (const float*)d_in[i]; break;   // pyr1
            case 19660800: w1  = (const float*)d_in[i]; break;   // win1
            case 131072:   p2  = (const float*)d_in[i]; break;   // pyr2
            case 4915200:  w2  = (const float*)d_in[i]; break;   // win2
            case 32768:    p3  = (const float*)d_in[i]; break;   // pyr3
            case 1228800:  w3  = (const float*)d_in[i]; break;   // win3
        }
    }

    modulus_kernel<<<2720, 256>>>(p0, p1, p2, p3);   // 696320 threads
    pool_kernel<<<2100, 512>>>(w0, w1, w2, w3, img);
    finalize_kernel<<<5, 256>>>((float*)d_out);
}